// round 13
// baseline (speedup 1.0000x reference)
#include <cuda_runtime.h>
#include <cuda_bf16.h>
#include <cstdint>

#define NN 50000
#define EE 800000
#define PP 65536
#define NCHUNK ((NN + 1023) / 1024)

// ================= device scratch =================
__device__ int    g_cnt[NN];
__device__ int    g_cur[NN];
__device__ int    g_off[NN + 1];
__device__ int    g_part[NCHUNK];
__device__ float  g_deg_norm[NN];
__device__ int2   g_ew[EE];                        // {src, w*dn[src]}
__device__ __nv_bfloat16 g_fh[(size_t)NN * 512];   // concat hi [N,512]
__device__ __nv_bfloat16 g_fl[(size_t)NN * 512];   // concat lo [N,512]
__device__ __nv_bfloat16 g_wh[3][128 * 512];       // W^T hi per layer [n,k]
__device__ __nv_bfloat16 g_wl[3][128 * 512];       // W^T lo per layer [n,k]

// ================= small helpers =================
__device__ __forceinline__ uint32_t smem_u32(const void* p) {
    uint32_t a;
    asm("{ .reg .u64 t; cvta.to.shared.u64 t, %1; cvt.u32.u64 %0, t; }" : "=r"(a) : "l"(p));
    return a;
}
__device__ __forceinline__ void ldsm4(uint32_t& r0, uint32_t& r1, uint32_t& r2,
                                      uint32_t& r3, uint32_t addr) {
    asm volatile("ldmatrix.sync.aligned.m8n8.x4.shared.b16 {%0,%1,%2,%3}, [%4];"
                 : "=r"(r0), "=r"(r1), "=r"(r2), "=r"(r3) : "r"(addr));
}
__device__ __forceinline__ void mma16816(float* c, const uint32_t* a, const uint32_t* b) {
    asm volatile(
        "mma.sync.aligned.m16n8k16.row.col.f32.bf16.bf16.f32 "
        "{%0,%1,%2,%3}, {%4,%5,%6,%7}, {%8,%9}, {%0,%1,%2,%3};"
        : "+f"(c[0]), "+f"(c[1]), "+f"(c[2]), "+f"(c[3])
        : "r"(a[0]), "r"(a[1]), "r"(a[2]), "r"(a[3]), "r"(b[0]), "r"(b[1]));
}
__device__ __forceinline__ void cp16(uint32_t saddr, const void* g, bool pred) {
    int sz = pred ? 16 : 0;
    asm volatile("cp.async.cg.shared.global [%0], [%1], 16, %2;"
                 :: "r"(saddr), "l"(g), "r"(sz));
}
__device__ __forceinline__ void cp16u(uint32_t saddr, const void* g) {
    asm volatile("cp.async.cg.shared.global [%0], [%1], 16;" :: "r"(saddr), "l"(g));
}
__device__ __forceinline__ void cp_commit() {
    asm volatile("cp.async.commit_group;" ::: "memory");
}
template <int N>
__device__ __forceinline__ void cp_wait() {
    asm volatile("cp.async.wait_group %0;" :: "n"(N) : "memory");
}

// ================= CSR build =================
__global__ void zero_k() {
    int i = blockIdx.x * blockDim.x + threadIdx.x;
    if (i < NN) { g_cnt[i] = 0; g_cur[i] = 0; }
}
__global__ void count_k(const int* __restrict__ dst) {
    int e = blockIdx.x * blockDim.x + threadIdx.x;
    if (e < EE) atomicAdd(&g_cnt[dst[e]], 1);
}
__global__ void degnorm_k() {
    int i = blockIdx.x * blockDim.x + threadIdx.x;
    if (i < NN) g_deg_norm[i] = rsqrtf(fmaxf((float)g_cnt[i], 1.0f));
}
__global__ void scan1_k() {
    __shared__ int wsum[32];
    int lane = threadIdx.x & 31, wid = threadIdx.x >> 5;
    int i = blockIdx.x * 1024 + threadIdx.x;
    int v = (i < NN) ? g_cnt[i] : 0;
    int s = v;
    #pragma unroll
    for (int o = 1; o < 32; o <<= 1) {
        int n = __shfl_up_sync(0xffffffffu, s, o);
        if (lane >= o) s += n;
    }
    if (lane == 31) wsum[wid] = s;
    __syncthreads();
    if (wid == 0) {
        int t = wsum[lane];
        #pragma unroll
        for (int o = 1; o < 32; o <<= 1) {
            int n = __shfl_up_sync(0xffffffffu, t, o);
            if (lane >= o) t += n;
        }
        wsum[lane] = t;
    }
    __syncthreads();
    int base = (wid > 0) ? wsum[wid - 1] : 0;
    if (i < NN) g_off[i] = base + s - v;
    if (threadIdx.x == 1023) g_part[blockIdx.x] = base + s;
}
__global__ void scan2_k() {
    int run = 0;
    for (int c = 0; c < NCHUNK; c++) { int v = g_part[c]; g_part[c] = run; run += v; }
    g_off[NN] = run;
}
__global__ void scan3_k() {
    int i = blockIdx.x * 1024 + threadIdx.x;
    if (i < NN) g_off[i] += g_part[blockIdx.x];
}
// scatter with deg_norm[src] folded into the edge weight
__global__ void scatter_k(const int* __restrict__ src, const int* __restrict__ dst,
                          const float* __restrict__ w) {
    int e = blockIdx.x * blockDim.x + threadIdx.x;
    if (e >= EE) return;
    int d = dst[e];
    int s = src[e];
    int p = g_off[d] + atomicAdd(&g_cur[d], 1);
    float ws = w[e] * g_deg_norm[s];
    g_ew[p] = make_int2(s, __float_as_int(ws));
}

// ================= hi/lo bf16 store =================
__device__ __forceinline__ void store_hilo(size_t idx, float4 f) {
    __nv_bfloat16 hx = __float2bfloat16_rn(f.x);
    __nv_bfloat16 hy = __float2bfloat16_rn(f.y);
    __nv_bfloat16 hz = __float2bfloat16_rn(f.z);
    __nv_bfloat16 hw = __float2bfloat16_rn(f.w);
    __nv_bfloat16 lx = __float2bfloat16_rn(f.x - __bfloat162float(hx));
    __nv_bfloat16 ly = __float2bfloat16_rn(f.y - __bfloat162float(hy));
    __nv_bfloat16 lz = __float2bfloat16_rn(f.z - __bfloat162float(hz));
    __nv_bfloat16 lw = __float2bfloat16_rn(f.w - __bfloat162float(hw));
    union { __nv_bfloat16 h[4]; uint2 u; } ph, pl;
    ph.h[0] = hx; ph.h[1] = hy; ph.h[2] = hz; ph.h[3] = hw;
    pl.h[0] = lx; pl.h[1] = ly; pl.h[2] = lz; pl.h[3] = lw;
    *reinterpret_cast<uint2*>(&g_fh[idx]) = ph.u;
    *reinterpret_cast<uint2*>(&g_fl[idx]) = pl.u;
}

// ================= layer-1 prep: fcat[:,0:128] = x (hi/lo) =================
__global__ void prep_k(const float* __restrict__ in) {
    int idx = blockIdx.x * blockDim.x + threadIdx.x;   // N*32
    if (idx >= NN * 32) return;
    int n = idx >> 5, q = idx & 31;
    float4 v = *reinterpret_cast<const float4*>(&in[(size_t)n * 128 + q * 4]);
    store_hilo((size_t)n * 512 + q * 4, v);
}

// ================= hop: gather hi/lo fcat cols [colofs-128,colofs) =================
__device__ __forceinline__ float4 gather_f(int s, int co) {
    size_t b = (size_t)s * 512 + co;
    uint2 uh = *reinterpret_cast<const uint2*>(&g_fh[b]);
    uint2 ul = *reinterpret_cast<const uint2*>(&g_fl[b]);
    float2 fh0 = __bfloat1622float2(*reinterpret_cast<__nv_bfloat162*>(&uh.x));
    float2 fh1 = __bfloat1622float2(*reinterpret_cast<__nv_bfloat162*>(&uh.y));
    float2 fl0 = __bfloat1622float2(*reinterpret_cast<__nv_bfloat162*>(&ul.x));
    float2 fl1 = __bfloat1622float2(*reinterpret_cast<__nv_bfloat162*>(&ul.y));
    return make_float4(fh0.x + fl0.x, fh0.y + fl0.y, fh1.x + fl1.x, fh1.y + fl1.y);
}

__global__ void hop_k(int colofs) {
    int gid = blockIdx.x * blockDim.x + threadIdx.x;
    int node = gid >> 5;
    int lane = gid & 31;
    if (node >= NN) return;
    int beg = g_off[node], end = g_off[node + 1];
    int co = colofs - 128 + lane * 4;
    float4 acc = make_float4(0.f, 0.f, 0.f, 0.f);
    int e = beg;
    for (; e + 3 < end; e += 4) {
        int2 e0 = g_ew[e],     e1 = g_ew[e + 1];
        int2 e2 = g_ew[e + 2], e3 = g_ew[e + 3];
        float w0 = __int_as_float(e0.y), w1 = __int_as_float(e1.y);
        float w2 = __int_as_float(e2.y), w3 = __int_as_float(e3.y);
        float4 v0 = gather_f(e0.x, co);
        float4 v1 = gather_f(e1.x, co);
        float4 v2 = gather_f(e2.x, co);
        float4 v3 = gather_f(e3.x, co);
        acc.x = fmaf(w0, v0.x, acc.x); acc.y = fmaf(w0, v0.y, acc.y);
        acc.z = fmaf(w0, v0.z, acc.z); acc.w = fmaf(w0, v0.w, acc.w);
        acc.x = fmaf(w1, v1.x, acc.x); acc.y = fmaf(w1, v1.y, acc.y);
        acc.z = fmaf(w1, v1.z, acc.z); acc.w = fmaf(w1, v1.w, acc.w);
        acc.x = fmaf(w2, v2.x, acc.x); acc.y = fmaf(w2, v2.y, acc.y);
        acc.z = fmaf(w2, v2.z, acc.z); acc.w = fmaf(w2, v2.w, acc.w);
        acc.x = fmaf(w3, v3.x, acc.x); acc.y = fmaf(w3, v3.y, acc.y);
        acc.z = fmaf(w3, v3.z, acc.z); acc.w = fmaf(w3, v3.w, acc.w);
    }
    for (; e < end; e++) {
        int2 ee = g_ew[e];
        float w = __int_as_float(ee.y);
        float4 v = gather_f(ee.x, co);
        acc.x = fmaf(w, v.x, acc.x); acc.y = fmaf(w, v.y, acc.y);
        acc.z = fmaf(w, v.z, acc.z); acc.w = fmaf(w, v.w, acc.w);
    }
    float dn = g_deg_norm[node];
    float4 f = make_float4(dn * acc.x, dn * acc.y, dn * acc.z, dn * acc.w);
    store_hilo((size_t)node * 512 + colofs + lane * 4, f);
}

// ================= W transpose + hi/lo split (all layers, one launch) =================
__global__ void convw_k(const float* __restrict__ W1, const float* __restrict__ W2,
                        const float* __restrict__ W3) {
    int i = blockIdx.x * blockDim.x + threadIdx.x;   // 0 .. 163839
    const float* W;
    int layer, ncols, li;
    if (i < 512 * 128)           { W = W1; layer = 0; ncols = 128; li = i; }
    else if (i < 2 * 512 * 128)  { W = W2; layer = 1; ncols = 128; li = i - 512 * 128; }
    else if (i < 2 * 512 * 128 + 512 * 64) { W = W3; layer = 2; ncols = 64; li = i - 2 * 512 * 128; }
    else return;
    int k = li / ncols, n = li % ncols;
    float v = W[li];
    __nv_bfloat16 h = __float2bfloat16_rn(v);
    __nv_bfloat16 l = __float2bfloat16_rn(v - __bfloat162float(h));
    g_wh[layer][(size_t)n * 512 + k] = h;
    g_wl[layer][(size_t)n * 512 + k] = l;
}

// ================= HMMA GEMM (double-buffered cp.async) =================
// C = fcat[M,512] @ W[512,BN] + bias.  3-pass hi/lo bf16, fp32 accum.
// TO_FCAT: relu, write hi/lo into fcat cols [0,128). else: write fp32 C.
template <int BN, bool TO_FCAT>
__global__ __launch_bounds__(256, 2)
void hmma_gemm_k(const float* __restrict__ bias, float* __restrict__ C, int M, int layer) {
    constexpr int PAD = 40;
    constexpr int A_MAT = 128 * PAD;
    constexpr int B_MAT = BN * PAD;
    constexpr int NT = BN / 16;
    constexpr int NP = NT / 2;
    constexpr int NB_LD = BN * 8 / 256;
    extern __shared__ __nv_bfloat16 sm[];

    int t = threadIdx.x;
    int wid = t >> 5, lane = t & 31;
    int wm = wid & 3, wn = wid >> 2;
    int row0 = blockIdx.x * 128;

    const __nv_bfloat16* Bh = g_wh[layer];
    const __nv_bfloat16* Bl = g_wl[layer];

    auto sAo = [&](int buf, int mat) { return (buf * 2 + mat) * A_MAT; };
    auto sBo = [&](int buf, int mat) { return 4 * A_MAT + (buf * 2 + mat) * B_MAT; };
    uint32_t smb = smem_u32(sm);

    auto prefetch = [&](int kc, int buf) {
        int k0 = kc * 32;
        #pragma unroll
        for (int l = 0; l < 4; l++) {
            int idx = t + l * 256;
            int mat = idx >> 9, rem = idx & 511;
            int r = rem >> 2, g = rem & 3;
            int gr = row0 + r;
            const __nv_bfloat16* srcm = mat ? g_fl : g_fh;
            cp16(smb + (sAo(buf, mat) + r * PAD + g * 8) * 2,
                 &srcm[(size_t)gr * 512 + k0 + g * 8], gr < M);
        }
        #pragma unroll
        for (int l = 0; l < NB_LD; l++) {
            int idx = t + l * 256;
            int mat = idx / (BN * 4), rem = idx % (BN * 4);
            int r = rem >> 2, g = rem & 3;
            const __nv_bfloat16* srcm = mat ? Bl : Bh;
            cp16u(smb + (sBo(buf, mat) + r * PAD + g * 8) * 2,
                  &srcm[(size_t)r * 512 + k0 + g * 8]);
        }
        cp_commit();
    };

    float acc[2][NT][4];
    #pragma unroll
    for (int i = 0; i < 2; i++)
        #pragma unroll
        for (int j = 0; j < NT; j++)
            #pragma unroll
            for (int q = 0; q < 4; q++) acc[i][j][q] = 0.f;

    prefetch(0, 0);

    for (int kc = 0; kc < 16; kc++) {
        int buf = kc & 1;
        if (kc + 1 < 16) prefetch(kc + 1, (kc + 1) & 1);
        if (kc + 1 < 16) cp_wait<1>(); else cp_wait<0>();
        __syncthreads();

        #pragma unroll
        for (int k16 = 0; k16 < 2; k16++) {
            int colb = k16 * 16 + (lane >> 4) * 8;
            uint32_t ah[2][4], al[2][4];
            #pragma unroll
            for (int mt = 0; mt < 2; mt++) {
                int r = wm * 32 + mt * 16 + (lane & 15);
                ldsm4(ah[mt][0], ah[mt][1], ah[mt][2], ah[mt][3],
                      smb + (sAo(buf, 0) + r * PAD + colb) * 2);
                ldsm4(al[mt][0], al[mt][1], al[mt][2], al[mt][3],
                      smb + (sAo(buf, 1) + r * PAD + colb) * 2);
            }
            #pragma unroll
            for (int np = 0; np < NP; np++) {
                int r = wn * (BN / 2) + np * 16 + (lane & 15);
                uint32_t h0, h1, h2, h3, l0, l1, l2, l3;
                ldsm4(h0, h1, h2, h3, smb + (sBo(buf, 0) + r * PAD + colb) * 2);
                ldsm4(l0, l1, l2, l3, smb + (sBo(buf, 1) + r * PAD + colb) * 2);
                uint32_t bh0[2] = {h0, h2}, bh1[2] = {h1, h3};
                uint32_t bl0[2] = {l0, l2}, bl1[2] = {l1, l3};
                #pragma unroll
                for (int mt = 0; mt < 2; mt++) {
                    mma16816(acc[mt][np * 2 + 0], ah[mt], bh0);
                    mma16816(acc[mt][np * 2 + 0], ah[mt], bl0);
                    mma16816(acc[mt][np * 2 + 0], al[mt], bh0);
                    mma16816(acc[mt][np * 2 + 1], ah[mt], bh1);
                    mma16816(acc[mt][np * 2 + 1], ah[mt], bl1);
                    mma16816(acc[mt][np * 2 + 1], al[mt], bh1);
                }
            }
        }
        __syncthreads();
    }

    // ---- epilogue ----
    #pragma unroll
    for (int mt = 0; mt < 2; mt++) {
        int r_lo = row0 + wm * 32 + mt * 16 + (lane >> 2);
        #pragma unroll
        for (int nt = 0; nt < NT; nt++) {
            int col = wn * (BN / 2) + nt * 8 + (lane & 3) * 2;
            float b0 = bias[col], b1 = bias[col + 1];
            float v0 = acc[mt][nt][0] + b0;
            float v1 = acc[mt][nt][1] + b1;
            float v2 = acc[mt][nt][2] + b0;
            float v3 = acc[mt][nt][3] + b1;
            if (TO_FCAT) {
                v0 = fmaxf(v0, 0.f); v1 = fmaxf(v1, 0.f);
                v2 = fmaxf(v2, 0.f); v3 = fmaxf(v3, 0.f);
                auto wr = [&](int r, float a, float b) {
                    if (r >= M) return;
                    __nv_bfloat16 ha = __float2bfloat16_rn(a);
                    __nv_bfloat16 hb = __float2bfloat16_rn(b);
                    __nv_bfloat16 la = __float2bfloat16_rn(a - __bfloat162float(ha));
                    __nv_bfloat16 lb = __float2bfloat16_rn(b - __bfloat162float(hb));
                    __nv_bfloat162 ph; ph.x = ha; ph.y = hb;
                    __nv_bfloat162 pl; pl.x = la; pl.y = lb;
                    *reinterpret_cast<__nv_bfloat162*>(&g_fh[(size_t)r * 512 + col]) = ph;
                    *reinterpret_cast<__nv_bfloat162*>(&g_fl[(size_t)r * 512 + col]) = pl;
                };
                wr(r_lo, v0, v1);
                wr(r_lo + 8, v2, v3);
            } else {
                if (r_lo < M)
                    *reinterpret_cast<float2*>(&C[(size_t)r_lo * BN + col]) =
                        make_float2(v0, v1);
                if (r_lo + 8 < M)
                    *reinterpret_cast<float2*>(&C[(size_t)(r_lo + 8) * BN + col]) =
                        make_float2(v2, v3);
            }
        }
    }
}

// ================= predictor =================
__global__ __launch_bounds__(256)
void pred_k(const int* __restrict__ pa, const int* __restrict__ pb,
            const int* __restrict__ na, const int* __restrict__ nb,
            const float* __restrict__ h,
            const float* __restrict__ P1, const float* __restrict__ pb1,
            const float* __restrict__ P2, const float* __restrict__ pb2,
            const float* __restrict__ P3, const float* __restrict__ pb3,
            float* __restrict__ out) {
    __shared__ float sP1[64 * 32];
    __shared__ float sP2[32 * 16];
    __shared__ float sP3[16];
    __shared__ float sb1[32];
    __shared__ float sb2[16];
    __shared__ float sb3;
    __shared__ float sz[8][64];
    int t = threadIdx.x;
    for (int i = t; i < 2048; i += 256) sP1[i] = P1[i];
    for (int i = t; i < 512; i += 256) sP2[i] = P2[i];
    if (t < 16) sP3[t] = P3[t];
    if (t < 32) sb1[t] = pb1[t];
    if (t < 16) sb2[t] = pb2[t];
    if (t == 0) sb3 = pb3[0];
    __syncthreads();
    int w = t >> 5, lane = t & 31;
    int gw = blockIdx.x * 8 + w;
    int nwarps = gridDim.x * 8;
    for (int p = gw; p < 2 * PP; p += nwarps) {
        int a, b;
        if (p < PP) { a = pa[p]; b = pb[p]; }
        else        { a = na[p - PP]; b = nb[p - PP]; }
        float2 ha = *reinterpret_cast<const float2*>(&h[(size_t)a * 64 + lane * 2]);
        float2 hb = *reinterpret_cast<const float2*>(&h[(size_t)b * 64 + lane * 2]);
        sz[w][lane * 2]     = ha.x * hb.x;
        sz[w][lane * 2 + 1] = ha.y * hb.y;
        __syncwarp();
        float acc = sb1[lane];
        #pragma unroll
        for (int i = 0; i < 64; i++) acc = fmaf(sz[w][i], sP1[i * 32 + lane], acc);
        acc = acc > 0.f ? acc : 0.2f * acc;
        __syncwarp();
        sz[w][lane] = acc;
        __syncwarp();
        float acc2 = 0.f;
        if (lane < 16) {
            acc2 = sb2[lane];
            #pragma unroll
            for (int i = 0; i < 32; i++) acc2 = fmaf(sz[w][i], sP2[i * 16 + lane], acc2);
            acc2 = acc2 > 0.f ? acc2 : 0.2f * acc2;
        }
        __syncwarp();
        if (lane < 16) sz[w][lane] = acc2 * sP3[lane];
        __syncwarp();
        if (lane == 0) {
            float s = sb3;
            #pragma unroll
            for (int i = 0; i < 16; i++) s += sz[w][i];
            out[p] = s;
        }
        __syncwarp();
    }
}

// ================= host launcher =================
extern "C" void kernel_launch(void* const* d_in, const int* in_sizes, int n_in,
                              void* d_out, int out_size) {
    const float* x       = (const float*)d_in[0];
    const int*   src     = (const int*)d_in[1];
    const int*   dst     = (const int*)d_in[2];
    const float* w_edge  = (const float*)d_in[3];
    const int*   pos_src = (const int*)d_in[4];
    const int*   pos_dst = (const int*)d_in[5];
    const int*   neg_src = (const int*)d_in[6];
    const int*   neg_dst = (const int*)d_in[7];
    const float* W1 = (const float*)d_in[8];
    const float* b1 = (const float*)d_in[9];
    const float* W2 = (const float*)d_in[10];
    const float* b2 = (const float*)d_in[11];
    const float* W3 = (const float*)d_in[12];
    const float* b3 = (const float*)d_in[13];
    const float* P1 = (const float*)d_in[14];
    const float* pb1 = (const float*)d_in[15];
    const float* P2 = (const float*)d_in[16];
    const float* pb2 = (const float*)d_in[17];
    const float* P3 = (const float*)d_in[18];
    const float* pb3 = (const float*)d_in[19];

    float* out = (float*)d_out;
    float* out_pos = out;                 // [P],[P],[N,64]
    float* out_h   = out + 2 * PP;

    constexpr int SMEM128 = (4 * 128 * 40 + 4 * 128 * 40) * 2;   // 81920
    constexpr int SMEM64  = (4 * 128 * 40 + 4 * 64 * 40) * 2;    // 61440

    static bool init = false;
    if (!init) {
        cudaFuncSetAttribute(hmma_gemm_k<128, true>,
                             cudaFuncAttributeMaxDynamicSharedMemorySize, SMEM128);
        cudaFuncSetAttribute(hmma_gemm_k<64, false>,
                             cudaFuncAttributeMaxDynamicSharedMemorySize, SMEM64);
        init = true;
    }

    const int TB = 256;
    int nb_N  = (NN + TB - 1) / TB;
    int nb_E  = (EE + TB - 1) / TB;
    int nb_hop = (NN * 32 + TB - 1) / TB;
    int nb_gemm = (NN + 127) / 128;

    // CSR build (deg_norm folded into edge weights at scatter)
    zero_k<<<nb_N, TB>>>();
    count_k<<<nb_E, TB>>>(dst);
    degnorm_k<<<nb_N, TB>>>();
    scan1_k<<<NCHUNK, 1024>>>();
    scan2_k<<<1, 1>>>();
    scan3_k<<<NCHUNK, 1024>>>();
    scatter_k<<<nb_E, TB>>>(src, dst, w_edge);

    // weight transpose + hi/lo split (single launch)
    convw_k<<<(2 * 512 * 128 + 512 * 64 + TB - 1) / TB, TB>>>(W1, W2, W3);

    // ---- layer 1 ----
    prep_k<<<nb_hop, TB>>>(x);
    hop_k<<<nb_hop, TB>>>(128);
    hop_k<<<nb_hop, TB>>>(256);
    hop_k<<<nb_hop, TB>>>(384);
    hmma_gemm_k<128, true><<<nb_gemm, 256, SMEM128>>>(b1, nullptr, NN, 0);

    // ---- layer 2 ----
    hop_k<<<nb_hop, TB>>>(128);
    hop_k<<<nb_hop, TB>>>(256);
    hop_k<<<nb_hop, TB>>>(384);
    hmma_gemm_k<128, true><<<nb_gemm, 256, SMEM128>>>(b2, nullptr, NN, 1);

    // ---- layer 3 ----
    hop_k<<<nb_hop, TB>>>(128);
    hop_k<<<nb_hop, TB>>>(256);
    hop_k<<<nb_hop, TB>>>(384);
    hmma_gemm_k<64, false><<<nb_gemm, 256, SMEM64>>>(b3, out_h, NN, 2);

    // ---- predictor (pos+neg fused) ----
    pred_k<<<1024, 256>>>(pos_src, pos_dst, neg_src, neg_dst, out_h,
                          P1, pb1, P2, pb2, P3, pb3, out_pos);
}